// round 10
// baseline (speedup 1.0000x reference)
#include <cuda_runtime.h>
#include <cuda_fp16.h>
#include <math.h>
#include <stdint.h>

// Problem constants
#define Bn 2
#define Tn 32
#define Nn 64
#define FINn 64
#define FOUTn 64
#define EDIMn 16
#define BT (Bn*Tn)            // 64
#define ROWS (BT*Nn)          // 4096
#define NBLK 256              // all CTAs co-resident: 2/SM * 148 = 296 >= 256

// -------- device scratch --------
__device__ __half g_hh[Bn*EDIMn*Nn*Nn];    // h hi   [b][e][i][j]
__device__ __half g_hl[Bn*EDIMn*Nn*Nn];    // h lo
__device__ __half g_w2[EDIMn*FINn*FOUTn];  // ew2 fp16 [e][f][o]
__device__ __half g_nw[FINn*FOUTn];        // nw fp16 [f][o]
__device__ float g_part[4][BT*Nn*FOUTn];   // per-eg partials (node-lin in eg0)
__device__ unsigned g_bcnt;                // global barrier counter (ends at 0)
__device__ unsigned g_btcnt[BT];           // per-bt completion counters (end at 0)

__device__ __forceinline__ float gelu_exact(float v) {
    return 0.5f * v * (1.0f + erff(v * 0.70710678118654752f));
}
__device__ __forceinline__ void split_f16(float v, __half& h, __half& l) {
    h = __float2half_rn(v);
    l = __float2half_rn(v - __half2float(h));
}
__device__ __forceinline__ uint32_t pack_f16(__half a, __half b) {
    return ((uint32_t)__half_as_ushort(b) << 16) | (uint32_t)__half_as_ushort(a);
}
__device__ __forceinline__ uint32_t smem_u32(const void* p) {
    uint32_t a;
    asm("{ .reg .u64 t; cvta.to.shared.u64 t, %1; cvt.u32.u64 %0, t; }" : "=r"(a) : "l"(p));
    return a;
}

#define LDM_X4(r0,r1,r2,r3,addr) \
    asm volatile("ldmatrix.sync.aligned.m8n8.x4.shared.b16 {%0,%1,%2,%3}, [%4];" \
        : "=r"(r0),"=r"(r1),"=r"(r2),"=r"(r3) : "r"(addr))
#define LDM_X4T(r0,r1,r2,r3,addr) \
    asm volatile("ldmatrix.sync.aligned.m8n8.x4.trans.shared.b16 {%0,%1,%2,%3}, [%4];" \
        : "=r"(r0),"=r"(r1),"=r"(r2),"=r"(r3) : "r"(addr))

__device__ __forceinline__ void mma_f16(float* c, const uint32_t* a, uint32_t b0, uint32_t b1) {
    asm volatile("mma.sync.aligned.m16n8k16.row.col.f32.f16.f16.f32 "
        "{%0,%1,%2,%3}, {%4,%5,%6,%7}, {%8,%9}, {%0,%1,%2,%3};"
        : "+f"(c[0]), "+f"(c[1]), "+f"(c[2]), "+f"(c[3])
        : "r"(a[0]), "r"(a[1]), "r"(a[2]), "r"(a[3]), "r"(b0), "r"(b1));
}

#define CP_ASYNC16(saddr, gptr) \
    asm volatile("cp.async.cg.shared.global [%0], [%1], 16;" \
        :: "r"(saddr), "l"(__cvta_generic_to_global(gptr)) : "memory")
#define CP_COMMIT() asm volatile("cp.async.commit_group;" ::: "memory")
#define CP_WAIT0()  asm volatile("cp.async.wait_group 0;" ::: "memory")

// Single global barrier: atomicInc wrapping at NBLK-1 -> last arrival sets 0.
__device__ __forceinline__ void gbar() {
    __syncthreads();
    if (threadIdx.x == 0) {
        __threadfence();
        atomicInc(&g_bcnt, NBLK - 1u);
        volatile unsigned* p = &g_bcnt;
        while (*p != 0u) {}
        __threadfence();
    }
    __syncthreads();
}

#define LDA 72
#define TILE (64*LDA)          // 4608 halves = 9216 B
#define FUS_SMEM (9*TILE*2)    // 82944 B: X(2) + W(2buf, doubles as x fp32 stage) + H(4) + P(1)

__global__ void __launch_bounds__(256, 2)
k_all(const float* __restrict__ x,   const float* __restrict__ adj,
      const float* __restrict__ ew1, const float* __restrict__ eb1,
      const float* __restrict__ ew2, const float* __restrict__ eb2,
      const float* __restrict__ nw,  const float* __restrict__ nb,
      const float* __restrict__ gw,  const float* __restrict__ gb,
      const float* __restrict__ gms, float* __restrict__ out) {
    extern __shared__ __align__(16) __half ds[];
    __shared__ float nsA[256], nsB[256];
    __shared__ float nsMul[64], nsSub[64], nsAdd[64], sS[64];
    __shared__ unsigned s_old;
    int tid = threadIdx.x, blk = blockIdx.x;

    // =================== PHASE A: shared products only (balanced) ===================
    if (blk < 16) {                             // nw convert: 4096 elems
        int idx = blk * 256 + tid;
        g_nw[idx] = __float2half_rn(nw[idx]);
    }
    {   // edge: 131072 elems, 2/thread, h[b][e][i][j] hi/lo
        int idx2 = blk * 512 + tid * 2;
        int row = idx2 >> 6;
        int j = idx2 & 63;
        int b = row >> 10, e = (row >> 6) & 15, i = row & 63;
        float2 a2 = *(const float2*)(adj + b * 4096 + i * 64 + j);
        float w1 = ew1[e], b1 = eb1[e];
        __half h0,l0,h1,l1;
        split_f16(gelu_exact(a2.x * w1 + b1), h0, l0);
        split_f16(gelu_exact(a2.y * w1 + b1), h1, l1);
        *(uint32_t*)(g_hh + idx2) = pack_f16(h0, h1);
        *(uint32_t*)(g_hl + idx2) = pack_f16(l0, l1);
    }
    {   // ew2 convert: 65536 elems, 1/thread
        int idx = blk * 256 + tid;
        g_w2[idx] = __float2half_rn(ew2[idx]);
    }

    gbar();

    // =================== PHASE B: local norm + fused GEMM + finisher ===================
    {
        __half *Xh = ds,          *Xl = ds + TILE;
        __half *Wb[2]  = { ds + 2*TILE, ds + 3*TILE };
        __half *Hhb[2] = { ds + 4*TILE, ds + 5*TILE };
        __half *Hlb[2] = { ds + 6*TILE, ds + 7*TILE };
        __half *Pt = ds + 8*TILE;
        float* xs = (float*)(ds + 2*TILE);      // fp32 x stage overlays W buffers

        int warp = tid >> 5, lane = tid & 31;
        int wr = warp >> 1, wc = warp & 1;
        int bt = blk >> 2, eg = blk & 3;
        int b = bt >> 5;

        // prefetch H(e0) + x[bt]
        {
            int e = eg * 4;
            uint32_t sHh = smem_u32(Hhb[0]), sHl = smem_u32(Hlb[0]);
            const __half* hhp = g_hh + (b * 16 + e) * 4096;
            const __half* hlp = g_hl + (b * 16 + e) * 4096;
#pragma unroll
            for (int l = 0; l < 2; l++) {
                int idx = tid + l * 256;
                int r = idx >> 3, q = idx & 7;
                uint32_t off = (uint32_t)(r * LDA + q * 8) * 2;
                CP_ASYNC16(sHh + off, hhp + r * 64 + q * 8);
                CP_ASYNC16(sHl + off, hlp + r * 64 + q * 8);
            }
            uint32_t sXs = smem_u32(xs);
            const float* xp = x + bt * 4096;
#pragma unroll
            for (int l = 0; l < 4; l++) {
                int idx = tid + l * 256;        // 1024 uint4
                CP_ASYNC16(sXs + idx * 16, xp + idx * 4);
            }
            CP_COMMIT();
        }
        CP_WAIT0();
        __syncthreads();

        // ---- block-local GraphNorm (from smem x) ----
        int f = tid & 63, g4 = tid >> 6;
        {
            float s = 0.f, ss = 0.f;
#pragma unroll
            for (int n = g4 * 16; n < g4 * 16 + 16; n++) {
                float v = xs[n * 64 + f];
                s += v; ss += v * v;
            }
            nsA[g4 * 64 + f] = s; nsB[g4 * 64 + f] = ss;
        }
        __syncthreads();
        if (g4 == 0) {
            float st  = nsA[f] + nsA[64 + f] + nsA[128 + f] + nsA[192 + f];
            float sst = nsB[f] + nsB[64 + f] + nsB[128 + f] + nsB[192 + f];
            float mean = st * (1.0f / Nn);
            float var  = sst * (1.0f / Nn) - mean * mean;
            float rstd = rsqrtf(var + 1e-5f);
            float w = gw[f], bbv = gb[f];
            float sub = mean * gms[0];
            nsMul[f] = rstd * w;
            nsSub[f] = sub;
            nsAdd[f] = bbv;
            sS[f]    = (float)Nn * ((mean - sub) * rstd * w + bbv);
        }
        __syncthreads();
        {
            float mul = nsMul[f], sub = nsSub[f], add = nsAdd[f];
#pragma unroll
            for (int n = g4 * 16; n < g4 * 16 + 16; n++) {
                float v = (xs[n * 64 + f] - sub) * mul + add;
                __half h, l; split_f16(v, h, l);
                Xh[n * LDA + f] = h;
                Xl[n * LDA + f] = l;
            }
        }
        __syncthreads();            // X ready; xs (= W region) fully consumed

        // cp.async W(e0) into Wb[0]
        {
            const __half* wp = g_w2 + (eg * 4) * 4096;
            uint32_t sW = smem_u32(Wb[0]);
#pragma unroll
            for (int l = 0; l < 2; l++) {
                int idx = tid + l * 256;
                int r = idx >> 3, q = idx & 7;
                CP_ASYNC16(sW + (uint32_t)(r * LDA + q * 8) * 2, wp + r * 64 + q * 8);
            }
            CP_COMMIT();
        }

        uint32_t xBh = smem_u32(Xh), xBl = smem_u32(Xl);
        uint32_t pB = smem_u32(Pt);

        int g = lane >> 3, lr = lane & 7;
        int arow = wr * 16 + (g & 1) * 8 + lr;
        int acol0 = (g >> 1) * 8;

        // persistent xn A-fragments (overlaps W(e0) cp.async)
        uint32_t xh[16], xl[16];
#pragma unroll
        for (int ks = 0; ks < 4; ks++) {
            uint32_t off = (uint32_t)(arow * LDA + ks * 16 + acol0) * 2;
            LDM_X4(xh[4*ks], xh[4*ks+1], xh[4*ks+2], xh[4*ks+3], xBh + off);
            LDM_X4(xl[4*ks], xl[4*ks+1], xl[4*ks+2], xl[4*ks+3], xBl + off);
        }
        CP_WAIT0();
        __syncthreads();

        float agg[4][4];
#pragma unroll
        for (int i = 0; i < 4; i++) { agg[i][0]=0.f; agg[i][1]=0.f; agg[i][2]=0.f; agg[i][3]=0.f; }

        int cr = lane >> 2, cc2 = (lane & 3) * 2;

        for (int ee = 0; ee < 4; ee++) {
            int cur = ee & 1, nxt = cur ^ 1;
            uint32_t wB = smem_u32(Wb[cur]);
            uint32_t hBh = smem_u32(Hhb[cur]), hBl = smem_u32(Hlb[cur]);

            // prefetch next e tiles
            if (ee < 3) {
                int e = eg * 4 + ee + 1;
                uint32_t sW = smem_u32(Wb[nxt]), sHh = smem_u32(Hhb[nxt]), sHl = smem_u32(Hlb[nxt]);
                const __half* wp = g_w2 + e * 4096;
                const __half* hhp = g_hh + (b * 16 + e) * 4096;
                const __half* hlp = g_hl + (b * 16 + e) * 4096;
#pragma unroll
                for (int l = 0; l < 2; l++) {
                    int idx = tid + l * 256;
                    int r = idx >> 3, q = idx & 7;
                    uint32_t off = (uint32_t)(r * LDA + q * 8) * 2;
                    CP_ASYNC16(sW + off,  wp  + r * 64 + q * 8);
                    CP_ASYNC16(sHh + off, hhp + r * 64 + q * 8);
                    CP_ASYNC16(sHl + off, hlp + r * 64 + q * 8);
                }
                CP_COMMIT();
            }

            // ---- mma1: P = (Xh+Xl) @ W_e ----
#pragma unroll
            for (int nt = 0; nt < 4; nt++) {
                float p[4] = {0.f,0.f,0.f,0.f};
                uint32_t bw[8];
                uint32_t off1 = (uint32_t)((g * 8 + lr) * LDA + wc * 32 + nt * 8) * 2;
                uint32_t off2 = (uint32_t)((32 + g * 8 + lr) * LDA + wc * 32 + nt * 8) * 2;
                LDM_X4T(bw[0], bw[1], bw[2], bw[3], wB + off1);
                LDM_X4T(bw[4], bw[5], bw[6], bw[7], wB + off2);
#pragma unroll
                for (int ks = 0; ks < 4; ks++) {
                    mma_f16(p, xh + 4*ks, bw[2*ks], bw[2*ks+1]);
                    mma_f16(p, xl + 4*ks, bw[2*ks], bw[2*ks+1]);
                }
#pragma unroll
                for (int half = 0; half < 2; half++) {
                    int row = wr * 16 + cr + half * 8;
                    int col = wc * 32 + nt * 8 + cc2;
                    *(uint32_t*)(Pt + row * LDA + col) =
                        pack_f16(__float2half_rn(p[half*2]), __float2half_rn(p[half*2+1]));
                }
            }
            __syncthreads();

            // ---- mma2: agg += (Hh+Hl) @ P ----
            uint32_t ahh[16], ahl[16];
#pragma unroll
            for (int ks = 0; ks < 4; ks++) {
                uint32_t off = (uint32_t)(arow * LDA + ks * 16 + acol0) * 2;
                LDM_X4(ahh[4*ks], ahh[4*ks+1], ahh[4*ks+2], ahh[4*ks+3], hBh + off);
                LDM_X4(ahl[4*ks], ahl[4*ks+1], ahl[4*ks+2], ahl[4*ks+3], hBl + off);
            }
#pragma unroll
            for (int kh = 0; kh < 2; kh++) {
#pragma unroll
                for (int nt = 0; nt < 4; nt++) {
                    uint32_t bp[4];
                    uint32_t off = (uint32_t)((kh * 32 + g * 8 + lr) * LDA + wc * 32 + nt * 8) * 2;
                    LDM_X4T(bp[0], bp[1], bp[2], bp[3], pB + off);
#pragma unroll
                    for (int k2 = 0; k2 < 2; k2++) {
                        int ks = kh * 2 + k2;
                        mma_f16(agg[nt], ahh + 4*ks, bp[2*k2], bp[2*k2+1]);
                        mma_f16(agg[nt], ahl + 4*ks, bp[2*k2], bp[2*k2+1]);
                    }
                }
            }
            if (ee < 3) CP_WAIT0();
            __syncthreads();
        }

        // ---- eg 0: node-lin  agg += (Xh+Xl) @ nw ----
        if (eg == 0) {
#pragma unroll
            for (int l = 0; l < 2; l++) {
                int idx = tid + l * 256;
                int r = idx >> 3, q = idx & 7;
                *(uint4*)(Wb[0] + r * LDA + q * 8) = *(const uint4*)(g_nw + r * 64 + q * 8);
            }
            __syncthreads();
            uint32_t wB = smem_u32(Wb[0]);
#pragma unroll
            for (int kh = 0; kh < 2; kh++) {
#pragma unroll
                for (int nt = 0; nt < 4; nt++) {
                    uint32_t bw[4];
                    uint32_t off = (uint32_t)((kh * 32 + g * 8 + lr) * LDA + wc * 32 + nt * 8) * 2;
                    LDM_X4T(bw[0], bw[1], bw[2], bw[3], wB + off);
#pragma unroll
                    for (int k2 = 0; k2 < 2; k2++) {
                        int ks = kh * 2 + k2;
                        mma_f16(agg[nt], xh + 4*ks, bw[2*k2], bw[2*k2+1]);
                        mma_f16(agg[nt], xl + 4*ks, bw[2*k2], bw[2*k2+1]);
                    }
                }
            }
        }

        // ---- store partial ----
        float* Cdst = g_part[eg] + bt * (Nn * FOUTn);
#pragma unroll
        for (int nt = 0; nt < 4; nt++) {
            int col = wc * 32 + nt * 8 + cc2;
            *(float2*)(Cdst + (wr * 16 + cr) * FOUTn + col)     = make_float2(agg[nt][0], agg[nt][1]);
            *(float2*)(Cdst + (wr * 16 + cr + 8) * FOUTn + col) = make_float2(agg[nt][2], agg[nt][3]);
        }

        // ---- per-bt finisher: last of 4 eg-blocks sums + T2 + gelu + out ----
        __threadfence();
        __syncthreads();
        if (tid == 0) s_old = atomicAdd(&g_btcnt[bt], 1u);
        __syncthreads();
        if (s_old == 3u) {
            __threadfence();
            // T2[o] = sum_f S[f]*eb2[f*64+o]  (4-group partial into nsA)
            {
                int o = f;
                float acc = 0.f;
#pragma unroll
                for (int ff = g4 * 16; ff < g4 * 16 + 16; ff++)
                    acc += sS[ff] * eb2[ff * FOUTn + o];
                nsA[g4 * 64 + o] = acc;
            }
            __syncthreads();
            int base = bt * (Nn * FOUTn);
#pragma unroll
            for (int l = 0; l < 4; l++) {
                int idx = tid + l * 256;          // 1024 float4 tasks for this bt
                int e0 = base + idx * 4;
                int o  = (idx * 4) & 63;
                float4 p0 = *(const float4*)(g_part[0] + e0);
                float4 p1 = *(const float4*)(g_part[1] + e0);
                float4 p2 = *(const float4*)(g_part[2] + e0);
                float4 p3 = *(const float4*)(g_part[3] + e0);
                float4 nbv = *(const float4*)(nb + o);
                float t20 = nsA[o]   + nsA[64+o]   + nsA[128+o]   + nsA[192+o];
                float t21 = nsA[o+1] + nsA[64+o+1] + nsA[128+o+1] + nsA[192+o+1];
                float t22 = nsA[o+2] + nsA[64+o+2] + nsA[128+o+2] + nsA[192+o+2];
                float t23 = nsA[o+3] + nsA[64+o+3] + nsA[128+o+3] + nsA[192+o+3];
                float v0 = p0.x + p1.x + p2.x + p3.x + nbv.x + t20;
                float v1 = p0.y + p1.y + p2.y + p3.y + nbv.y + t21;
                float v2 = p0.z + p1.z + p2.z + p3.z + nbv.z + t22;
                float v3 = p0.w + p1.w + p2.w + p3.w + nbv.w + t23;
                *(float4*)(out + e0) = make_float4(gelu_exact(v0), gelu_exact(v1),
                                                   gelu_exact(v2), gelu_exact(v3));
            }
            if (tid == 0) g_btcnt[bt] = 0;        // reset for next graph replay
        }
    }
}

extern "C" void kernel_launch(void* const* d_in, const int* in_sizes, int n_in,
                              void* d_out, int out_size) {
    const float* x   = (const float*)d_in[0];
    const float* adj = (const float*)d_in[1];
    const float* ew1 = (const float*)d_in[2];
    const float* eb1 = (const float*)d_in[3];
    const float* ew2 = (const float*)d_in[4];
    const float* eb2 = (const float*)d_in[5];
    const float* nw  = (const float*)d_in[6];
    const float* nb  = (const float*)d_in[7];
    const float* gw  = (const float*)d_in[8];
    const float* gb  = (const float*)d_in[9];
    const float* gms = (const float*)d_in[10];
    float* out = (float*)d_out;

    cudaFuncSetAttribute(k_all, cudaFuncAttributeMaxDynamicSharedMemorySize, FUS_SMEM);
    k_all<<<NBLK, 256, FUS_SMEM>>>(x, adj, ew1, eb1, ew2, eb2, nw, nb, gw, gb, gms, out);
}

// round 11
// speedup vs baseline: 1.2166x; 1.2166x over previous
#include <cuda_runtime.h>
#include <cuda_fp16.h>
#include <math.h>
#include <stdint.h>

// Problem constants
#define Bn 2
#define Tn 32
#define Nn 64
#define FINn 64
#define FOUTn 64
#define EDIMn 16
#define BT (Bn*Tn)            // 64
#define ROWS (BT*Nn)          // 4096
#define NBLK 256              // all CTAs co-resident: 2/SM * 148 = 296 >= 256

// -------- device scratch --------
__device__ __half g_xnh[ROWS*FINn];        // xn hi  [bt*64+j][f]
__device__ __half g_xnl[ROWS*FINn];        // xn lo
__device__ __half g_h[Bn*EDIMn*Nn*Nn];     // h fp16 [b][e][i][j]  (hi only)
__device__ __half g_w2[EDIMn*FINn*FOUTn];  // ew2 fp16 [e][f][o]
__device__ __half g_nw[FINn*FOUTn];        // nw fp16 [f][o]
__device__ float g_part[4][BT*Nn*FOUTn];   // per-eg partials (node-lin in eg0)
__device__ float g_T2[BT*FOUTn];           // eb2 contribution
__device__ unsigned g_bcnt;                // global barrier counter (ends at 0)
__device__ unsigned g_btcnt[BT];           // per-bt completion counters (end at 0)

__device__ __forceinline__ float gelu_exact(float v) {
    return 0.5f * v * (1.0f + erff(v * 0.70710678118654752f));
}
__device__ __forceinline__ void split_f16(float v, __half& h, __half& l) {
    h = __float2half_rn(v);
    l = __float2half_rn(v - __half2float(h));
}
__device__ __forceinline__ uint32_t pack_f16(__half a, __half b) {
    return ((uint32_t)__half_as_ushort(b) << 16) | (uint32_t)__half_as_ushort(a);
}
__device__ __forceinline__ uint32_t smem_u32(const void* p) {
    uint32_t a;
    asm("{ .reg .u64 t; cvta.to.shared.u64 t, %1; cvt.u32.u64 %0, t; }" : "=r"(a) : "l"(p));
    return a;
}

#define LDM_X4(r0,r1,r2,r3,addr) \
    asm volatile("ldmatrix.sync.aligned.m8n8.x4.shared.b16 {%0,%1,%2,%3}, [%4];" \
        : "=r"(r0),"=r"(r1),"=r"(r2),"=r"(r3) : "r"(addr))
#define LDM_X4T(r0,r1,r2,r3,addr) \
    asm volatile("ldmatrix.sync.aligned.m8n8.x4.trans.shared.b16 {%0,%1,%2,%3}, [%4];" \
        : "=r"(r0),"=r"(r1),"=r"(r2),"=r"(r3) : "r"(addr))

__device__ __forceinline__ void mma_f16(float* c, const uint32_t* a, uint32_t b0, uint32_t b1) {
    asm volatile("mma.sync.aligned.m16n8k16.row.col.f32.f16.f16.f32 "
        "{%0,%1,%2,%3}, {%4,%5,%6,%7}, {%8,%9}, {%0,%1,%2,%3};"
        : "+f"(c[0]), "+f"(c[1]), "+f"(c[2]), "+f"(c[3])
        : "r"(a[0]), "r"(a[1]), "r"(a[2]), "r"(a[3]), "r"(b0), "r"(b1));
}

#define CP_ASYNC16(saddr, gptr) \
    asm volatile("cp.async.cg.shared.global [%0], [%1], 16;" \
        :: "r"(saddr), "l"(__cvta_generic_to_global(gptr)) : "memory")
#define CP_COMMIT() asm volatile("cp.async.commit_group;" ::: "memory")
#define CP_WAIT0()  asm volatile("cp.async.wait_group 0;" ::: "memory")

// Single global barrier: atomicInc wrapping at NBLK-1 -> last arrival sets 0.
__device__ __forceinline__ void gbar() {
    __syncthreads();
    if (threadIdx.x == 0) {
        __threadfence();
        atomicInc(&g_bcnt, NBLK - 1u);
        volatile unsigned* p = &g_bcnt;
        while (*p != 0u) {}
        __threadfence();
    }
    __syncthreads();
}

#define LDA 72
#define TILE (64*LDA)           // 4608 halves
#define FUS_SMEM (10*TILE*2)    // 92160 B: X/P(2) + W(2x2buf) + H(2x2buf) -> 2 CTAs/SM

__global__ void __launch_bounds__(256, 2)
k_all(const float* __restrict__ x,   const float* __restrict__ adj,
      const float* __restrict__ ew1, const float* __restrict__ eb1,
      const float* __restrict__ ew2, const float* __restrict__ eb2,
      const float* __restrict__ nw,  const float* __restrict__ nb,
      const float* __restrict__ gw,  const float* __restrict__ gb,
      const float* __restrict__ gms, float* __restrict__ out) {
    extern __shared__ __align__(16) __half ds[];
    __shared__ unsigned s_old;
    int tid = threadIdx.x, blk = blockIdx.x;

    // =================== PHASE A: prologue ===================
    if (blk < BT) {
        // ---- norm + T2 for bt = blk (runs concurrently with edge blocks) ----
        int bt = blk;
        int f = tid & 63;
        int g = tid >> 6;
        float* sA   = (float*)ds;               // [4][64]
        float* sB   = sA + 256;
        float* sMul = sB + 256;
        float* sSub = sMul + 64;
        float* sAdd = sSub + 64;
        float* sSf  = sAdd + 64;

        const float* xp = x + bt * (Nn * FINn) + f;
        float s = 0.f, ss = 0.f;
#pragma unroll
        for (int n = g * 16; n < g * 16 + 16; n++) {
            float v = xp[n * FINn];
            s += v; ss += v * v;
        }
        sA[g * 64 + f] = s; sB[g * 64 + f] = ss;
        __syncthreads();

        if (g == 0) {
            float st  = sA[f] + sA[64 + f] + sA[128 + f] + sA[192 + f];
            float sst = sB[f] + sB[64 + f] + sB[128 + f] + sB[192 + f];
            float mean = st * (1.0f / Nn);
            float var  = sst * (1.0f / Nn) - mean * mean;
            float rstd = rsqrtf(var + 1e-5f);
            float w = gw[f], bbv = gb[f];
            float sub = mean * gms[0];
            sMul[f] = rstd * w;
            sSub[f] = sub;
            sAdd[f] = bbv;
            sSf[f]  = (float)Nn * ((mean - sub) * rstd * w + bbv);
        }
        __syncthreads();

        float mul = sMul[f], sub = sSub[f], add = sAdd[f];
#pragma unroll
        for (int n = g * 16; n < g * 16 + 16; n++) {
            float v = (xp[n * FINn] - sub) * mul + add;
            __half h, l; split_f16(v, h, l);
            g_xnh[bt * 4096 + n * 64 + f] = h;
            g_xnl[bt * 4096 + n * 64 + f] = l;
        }

        int o = f;
        float acc = 0.f;
#pragma unroll
        for (int ff = g * 16; ff < g * 16 + 16; ff++)
            acc += sSf[ff] * eb2[ff * FOUTn + o];
        __syncthreads();
        sA[g * 64 + o] = acc;
        __syncthreads();
        if (g == 0)
            g_T2[bt * FOUTn + o] = sA[o] + sA[64 + o] + sA[128 + o] + sA[192 + o];
        __syncthreads();
    } else if (blk < BT + 16) {
        // nw convert: 4096 elems over blocks 64..79
        int idx = (blk - BT) * 256 + tid;
        g_nw[idx] = __float2half_rn(nw[idx]);
    }

    // edge (all blocks): 131072 elems, 2/thread, fp16 hi only
    {
        int idx2 = blk * 512 + tid * 2;
        int row = idx2 >> 6;                    // (b,e,i)
        int j = idx2 & 63;
        int b = row >> 10, e = (row >> 6) & 15, i = row & 63;
        float2 a2 = *(const float2*)(adj + b * 4096 + i * 64 + j);
        float w1 = ew1[e], b1 = eb1[e];
        __half h0 = __float2half_rn(gelu_exact(a2.x * w1 + b1));
        __half h1 = __float2half_rn(gelu_exact(a2.y * w1 + b1));
        *(uint32_t*)(g_h + idx2) = pack_f16(h0, h1);
    }
    // ew2 convert (all blocks): 65536 elems, 1/thread
    {
        int idx = blk * 256 + tid;
        g_w2[idx] = __float2half_rn(ew2[idx]);
    }

    gbar();

    // =================== PHASE B: fused GEMM (paired e) + finisher ===================
    {
        __half *Xh = ds, *Xl = ds + TILE;       // recycled as P0/P1 after frags
        __half *P0 = Xh, *P1 = Xl;
        __half *Wt[2][2] = {{ds + 2*TILE, ds + 3*TILE}, {ds + 4*TILE, ds + 5*TILE}};
        __half *Ht[2][2] = {{ds + 6*TILE, ds + 7*TILE}, {ds + 8*TILE, ds + 9*TILE}};

        int warp = tid >> 5, lane = tid & 31;
        int wr = warp >> 1, wc = warp & 1;
        int bt = blk >> 2, eg = blk & 3;
        int b = bt >> 5;

        // prefetch X tiles + pair 0 (W/H for e0, e1)
        {
            const __half* xhp = g_xnh + bt * 4096;
            const __half* xlp = g_xnl + bt * 4096;
            uint32_t sXh = smem_u32(Xh), sXl = smem_u32(Xl);
#pragma unroll
            for (int l = 0; l < 2; l++) {
                int idx = tid + l * 256;
                int r = idx >> 3, q = idx & 7;
                uint32_t off = (uint32_t)(r * LDA + q * 8) * 2;
                CP_ASYNC16(sXh + off, xhp + r * 64 + q * 8);
                CP_ASYNC16(sXl + off, xlp + r * 64 + q * 8);
            }
#pragma unroll
            for (int e2 = 0; e2 < 2; e2++) {
                int e = eg * 4 + e2;
                uint32_t sW = smem_u32(Wt[0][e2]), sH = smem_u32(Ht[0][e2]);
                const __half* wp = g_w2 + e * 4096;
                const __half* hp = g_h + (b * 16 + e) * 4096;
#pragma unroll
                for (int l = 0; l < 2; l++) {
                    int idx = tid + l * 256;
                    int r = idx >> 3, q = idx & 7;
                    uint32_t off = (uint32_t)(r * LDA + q * 8) * 2;
                    CP_ASYNC16(sW + off, wp + r * 64 + q * 8);
                    CP_ASYNC16(sH + off, hp + r * 64 + q * 8);
                }
            }
            CP_COMMIT();
        }
        CP_WAIT0();
        __syncthreads();

        uint32_t xBh = smem_u32(Xh), xBl = smem_u32(Xl);
        int g = lane >> 3, lr = lane & 7;
        int arow = wr * 16 + (g & 1) * 8 + lr;
        int acol0 = (g >> 1) * 8;

        // persistent xn A-fragments, then X tiles become P0/P1
        uint32_t xh[16], xl[16];
#pragma unroll
        for (int ks = 0; ks < 4; ks++) {
            uint32_t off = (uint32_t)(arow * LDA + ks * 16 + acol0) * 2;
            LDM_X4(xh[4*ks], xh[4*ks+1], xh[4*ks+2], xh[4*ks+3], xBh + off);
            LDM_X4(xl[4*ks], xl[4*ks+1], xl[4*ks+2], xl[4*ks+3], xBl + off);
        }
        __syncthreads();            // all warps done reading X tiles

        // prefetch pair 1 (e2, e3)
        {
#pragma unroll
            for (int e2 = 0; e2 < 2; e2++) {
                int e = eg * 4 + 2 + e2;
                uint32_t sW = smem_u32(Wt[1][e2]), sH = smem_u32(Ht[1][e2]);
                const __half* wp = g_w2 + e * 4096;
                const __half* hp = g_h + (b * 16 + e) * 4096;
#pragma unroll
                for (int l = 0; l < 2; l++) {
                    int idx = tid + l * 256;
                    int r = idx >> 3, q = idx & 7;
                    uint32_t off = (uint32_t)(r * LDA + q * 8) * 2;
                    CP_ASYNC16(sW + off, wp + r * 64 + q * 8);
                    CP_ASYNC16(sH + off, hp + r * 64 + q * 8);
                }
            }
            CP_COMMIT();
        }

        float agg[4][4];
#pragma unroll
        for (int i = 0; i < 4; i++) { agg[i][0]=0.f; agg[i][1]=0.f; agg[i][2]=0.f; agg[i][3]=0.f; }

        int cr = lane >> 2, cc2 = (lane & 3) * 2;
        uint32_t pB[2] = { smem_u32(P0), smem_u32(P1) };

        for (int pp = 0; pp < 2; pp++) {
            // ---- mma1 for both e of the pair: P(e2) = (Xh+Xl) @ W ----
#pragma unroll
            for (int e2 = 0; e2 < 2; e2++) {
                uint32_t wB = smem_u32(Wt[pp][e2]);
                __half* Pt = e2 ? P1 : P0;
#pragma unroll
                for (int nt = 0; nt < 4; nt++) {
                    float p[4] = {0.f,0.f,0.f,0.f};
                    uint32_t bw[8];
                    uint32_t off1 = (uint32_t)((g * 8 + lr) * LDA + wc * 32 + nt * 8) * 2;
                    uint32_t off2 = (uint32_t)((32 + g * 8 + lr) * LDA + wc * 32 + nt * 8) * 2;
                    LDM_X4T(bw[0], bw[1], bw[2], bw[3], wB + off1);
                    LDM_X4T(bw[4], bw[5], bw[6], bw[7], wB + off2);
#pragma unroll
                    for (int ks = 0; ks < 4; ks++) {
                        mma_f16(p, xh + 4*ks, bw[2*ks], bw[2*ks+1]);
                        mma_f16(p, xl + 4*ks, bw[2*ks], bw[2*ks+1]);
                    }
#pragma unroll
                    for (int half = 0; half < 2; half++) {
                        int row = wr * 16 + cr + half * 8;
                        int col = wc * 32 + nt * 8 + cc2;
                        *(uint32_t*)(Pt + row * LDA + col) =
                            pack_f16(__float2half_rn(p[half*2]), __float2half_rn(p[half*2+1]));
                    }
                }
            }
            if (pp == 0) CP_WAIT0();
            __syncthreads();

            // ---- mma2 for both e: agg += h(e) @ P(e) ----
#pragma unroll
            for (int e2 = 0; e2 < 2; e2++) {
                uint32_t hB = smem_u32(Ht[pp][e2]);
                uint32_t ahh[16];
#pragma unroll
                for (int ks = 0; ks < 4; ks++) {
                    uint32_t off = (uint32_t)(arow * LDA + ks * 16 + acol0) * 2;
                    LDM_X4(ahh[4*ks], ahh[4*ks+1], ahh[4*ks+2], ahh[4*ks+3], hB + off);
                }
#pragma unroll
                for (int kh = 0; kh < 2; kh++) {
#pragma unroll
                    for (int nt = 0; nt < 4; nt++) {
                        uint32_t bp[4];
                        uint32_t off = (uint32_t)((kh * 32 + g * 8 + lr) * LDA + wc * 32 + nt * 8) * 2;
                        LDM_X4T(bp[0], bp[1], bp[2], bp[3], pB[e2] + off);
#pragma unroll
                        for (int k2 = 0; k2 < 2; k2++) {
                            int ks = kh * 2 + k2;
                            mma_f16(agg[nt], ahh + 4*ks, bp[2*k2], bp[2*k2+1]);
                        }
                    }
                }
            }
            __syncthreads();
        }

        // ---- eg 0: node-lin  agg += (Xh+Xl) @ nw ----
        if (eg == 0) {
#pragma unroll
            for (int l = 0; l < 2; l++) {
                int idx = tid + l * 256;
                int r = idx >> 3, q = idx & 7;
                *(uint4*)(Wt[0][0] + r * LDA + q * 8) = *(const uint4*)(g_nw + r * 64 + q * 8);
            }
            __syncthreads();
            uint32_t wB = smem_u32(Wt[0][0]);
#pragma unroll
            for (int kh = 0; kh < 2; kh++) {
#pragma unroll
                for (int nt = 0; nt < 4; nt++) {
                    uint32_t bw[4];
                    uint32_t off = (uint32_t)((kh * 32 + g * 8 + lr) * LDA + wc * 32 + nt * 8) * 2;
                    LDM_X4T(bw[0], bw[1], bw[2], bw[3], wB + off);
#pragma unroll
                    for (int k2 = 0; k2 < 2; k2++) {
                        int ks = kh * 2 + k2;
                        mma_f16(agg[nt], xh + 4*ks, bw[2*k2], bw[2*k2+1]);
                        mma_f16(agg[nt], xl + 4*ks, bw[2*k2], bw[2*k2+1]);
                    }
                }
            }
        }

        // ---- store partial ----
        float* Cdst = g_part[eg] + bt * (Nn * FOUTn);
#pragma unroll
        for (int nt = 0; nt < 4; nt++) {
            int col = wc * 32 + nt * 8 + cc2;
            *(float2*)(Cdst + (wr * 16 + cr) * FOUTn + col)     = make_float2(agg[nt][0], agg[nt][1]);
            *(float2*)(Cdst + (wr * 16 + cr + 8) * FOUTn + col) = make_float2(agg[nt][2], agg[nt][3]);
        }

        // ---- per-bt finisher: last of 4 eg-blocks sums + gelu + out ----
        __threadfence();
        __syncthreads();
        if (tid == 0) s_old = atomicAdd(&g_btcnt[bt], 1u);
        __syncthreads();
        if (s_old == 3u) {
            __threadfence();
            int base = bt * (Nn * FOUTn);
#pragma unroll
            for (int l = 0; l < 4; l++) {
                int idx = tid + l * 256;          // 1024 float4 tasks for this bt
                int e0 = base + idx * 4;
                int o  = (idx * 4) & 63;
                float4 p0 = *(const float4*)(g_part[0] + e0);
                float4 p1 = *(const float4*)(g_part[1] + e0);
                float4 p2 = *(const float4*)(g_part[2] + e0);
                float4 p3 = *(const float4*)(g_part[3] + e0);
                float4 nbv = *(const float4*)(nb + o);
                float4 t2v = *(const float4*)(g_T2 + bt * FOUTn + o);
                float v0 = p0.x + p1.x + p2.x + p3.x + nbv.x + t2v.x;
                float v1 = p0.y + p1.y + p2.y + p3.y + nbv.y + t2v.y;
                float v2 = p0.z + p1.z + p2.z + p3.z + nbv.z + t2v.z;
                float v3 = p0.w + p1.w + p2.w + p3.w + nbv.w + t2v.w;
                *(float4*)(out + e0) = make_float4(gelu_exact(v0), gelu_exact(v1),
                                                   gelu_exact(v2), gelu_exact(v3));
            }
            if (tid == 0) g_btcnt[bt] = 0;        // reset for next graph replay
        }
    }
}

extern "C" void kernel_launch(void* const* d_in, const int* in_sizes, int n_in,
                              void* d_out, int out_size) {
    const float* x   = (const float*)d_in[0];
    const float* adj = (const float*)d_in[1];
    const float* ew1 = (const float*)d_in[2];
    const float* eb1 = (const float*)d_in[3];
    const float* ew2 = (const float*)d_in[4];
    const float* eb2 = (const float*)d_in[5];
    const float* nw  = (const float*)d_in[6];
    const float* nb  = (const float*)d_in[7];
    const float* gw  = (const float*)d_in[8];
    const float* gb  = (const float*)d_in[9];
    const float* gms = (const float*)d_in[10];
    float* out = (float*)d_out;

    cudaFuncSetAttribute(k_all, cudaFuncAttributeMaxDynamicSharedMemorySize, FUS_SMEM);
    k_all<<<NBLK, 256, FUS_SMEM>>>(x, adj, ew1, eb1, ew2, eb2, nw, nb, gw, gb, gms, out);
}